// round 5
// baseline (speedup 1.0000x reference)
#include <cuda_runtime.h>
#include <math.h>

#define BB   256
#define SS   196
#define RNN  1024
#define ATTH 512
#define KSPLIT 8
#define KCHUNK (RNN / KSPLIT)   // 128

// Split-K partial results for att_h = h @ w_h2att^T  (bias folded in later).
// 8 * 256 * 512 * 4B = 4 MB device-global scratch (allowed; no allocation).
__device__ float g_atth_part[KSPLIT * BB * ATTH];

// ---------------------------------------------------------------------------
// Kernel 1: split-K tiled fp32 GEMM.
//   att_h_part[z][m][n] = sum_{k in chunk z} h[m][k] * w[n][k]
// Grid: (ATTH/64, BB/64, KSPLIT) = (8, 4, 8) = 256 blocks, 256 threads.
// ---------------------------------------------------------------------------
__global__ __launch_bounds__(256) void gemm_atth_kernel(
    const float* __restrict__ h, const float* __restrict__ w) {
  const int n0 = blockIdx.x * 64;
  const int m0 = blockIdx.y * 64;
  const int k0 = blockIdx.z * KCHUNK;

  __shared__ float As[16][65];
  __shared__ float Bs[16][65];

  const int t    = threadIdx.x;           // 0..255
  const int lrow = t >> 2;                 // 0..63
  const int lk4  = (t & 3) * 4;            // 0,4,8,12
  const int tx   = (t & 15) * 4;           // n micro-tile
  const int ty   = (t >> 4) * 4;           // m micro-tile

  float acc[4][4] = {};

  for (int kk = 0; kk < KCHUNK; kk += 16) {
    const float4 av = *(const float4*)(h + (size_t)(m0 + lrow) * RNN + k0 + kk + lk4);
    const float4 bv = *(const float4*)(w + (size_t)(n0 + lrow) * RNN + k0 + kk + lk4);
    __syncthreads();   // previous iteration's compute done before overwrite
    As[lk4 + 0][lrow] = av.x; As[lk4 + 1][lrow] = av.y;
    As[lk4 + 2][lrow] = av.z; As[lk4 + 3][lrow] = av.w;
    Bs[lk4 + 0][lrow] = bv.x; Bs[lk4 + 1][lrow] = bv.y;
    Bs[lk4 + 2][lrow] = bv.z; Bs[lk4 + 3][lrow] = bv.w;
    __syncthreads();
#pragma unroll
    for (int k = 0; k < 16; k++) {
      float a[4], b[4];
#pragma unroll
      for (int i = 0; i < 4; i++) a[i] = As[k][ty + i];
#pragma unroll
      for (int j = 0; j < 4; j++) b[j] = Bs[k][tx + j];
#pragma unroll
      for (int i = 0; i < 4; i++)
#pragma unroll
        for (int j = 0; j < 4; j++)
          acc[i][j] = fmaf(a[i], b[j], acc[i][j]);
    }
  }

  float* dst = g_atth_part + (size_t)blockIdx.z * BB * ATTH;
#pragma unroll
  for (int i = 0; i < 4; i++)
#pragma unroll
    for (int j = 0; j < 4; j++)
      dst[(size_t)(m0 + ty + i) * ATTH + (n0 + tx + j)] = acc[i][j];
}

// ---------------------------------------------------------------------------
// Kernel 2: fused per-batch attention.
//   scores[s] = sum_a tanh(p_att[b,s,a] + att_h[b,a] + bias[a]) * w_alpha[a]
//   weight    = softmax_s(scores)               (b_alpha dropped: shift-inv.)
//   out[b,d]  = sum_s weight[s] * att_feats[b,s,d]
// Grid: 256 blocks, 512 threads.
// ---------------------------------------------------------------------------
__global__ __launch_bounds__(512) void attn_fused_kernel(
    const float* __restrict__ att_feats,
    const float* __restrict__ p_att,
    const float* __restrict__ b_h2att,
    const float* __restrict__ w_alpha,
    float* __restrict__ out) {
  __shared__ __align__(16) float sh_atth[ATTH];
  __shared__ __align__(16) float sh_wa[ATTH];
  __shared__ float sh_sc[SS];

  const int b    = blockIdx.x;
  const int tid  = threadIdx.x;
  const int warp = tid >> 5;
  const int lane = tid & 31;

  // Sum split-K partials + bias into shared att_h; stage w_alpha.
  {
    float v = b_h2att[tid];
#pragma unroll
    for (int z = 0; z < KSPLIT; z++)
      v += g_atth_part[(size_t)z * BB * ATTH + (size_t)b * ATTH + tid];
    sh_atth[tid] = v;
    sh_wa[tid] = w_alpha[tid];
  }
  __syncthreads();

  // ---- Phase A: scores (one warp per s-row, strided) ----
  const float* pbase = p_att + (size_t)b * SS * ATTH;
  for (int s = warp; s < SS; s += 16) {
    const float* row = pbase + (size_t)s * ATTH;
    float acc = 0.f;
#pragma unroll
    for (int i = 0; i < 4; i++) {
      const int a = i * 128 + lane * 4;
      const float4 p  = *(const float4*)(row + a);
      const float4 ah = *(const float4*)(sh_atth + a);
      const float4 wa = *(const float4*)(sh_wa + a);
      acc += tanhf(p.x + ah.x) * wa.x;
      acc += tanhf(p.y + ah.y) * wa.y;
      acc += tanhf(p.z + ah.z) * wa.z;
      acc += tanhf(p.w + ah.w) * wa.w;
    }
#pragma unroll
    for (int off = 16; off > 0; off >>= 1)
      acc += __shfl_xor_sync(0xffffffffu, acc, off);
    if (lane == 0) sh_sc[s] = acc;
  }
  __syncthreads();

  // ---- Softmax over S (warp 0) ----
  if (warp == 0) {
    float m = -INFINITY;
    for (int s = lane; s < SS; s += 32) m = fmaxf(m, sh_sc[s]);
#pragma unroll
    for (int off = 16; off > 0; off >>= 1)
      m = fmaxf(m, __shfl_xor_sync(0xffffffffu, m, off));
    float sum = 0.f;
    for (int s = lane; s < SS; s += 32) {
      const float e = expf(sh_sc[s] - m);
      sh_sc[s] = e;
      sum += e;
    }
#pragma unroll
    for (int off = 16; off > 0; off >>= 1)
      sum += __shfl_xor_sync(0xffffffffu, sum, off);
    const float inv = 1.f / sum;
    for (int s = lane; s < SS; s += 32) sh_sc[s] *= inv;
  }
  __syncthreads();

  // ---- Phase B: weighted sum over att_feats (float2 per thread) ----
  const float* abase = att_feats + (size_t)b * SS * RNN + (size_t)tid * 2;
  float acc0 = 0.f, acc1 = 0.f;
#pragma unroll 4
  for (int s = 0; s < SS; s++) {
    const float ws = sh_sc[s];
    const float2 v = *(const float2*)(abase + (size_t)s * RNN);
    acc0 = fmaf(ws, v.x, acc0);
    acc1 = fmaf(ws, v.y, acc1);
  }
  *(float2*)(out + (size_t)b * RNN + (size_t)tid * 2) = make_float2(acc0, acc1);
}

// ---------------------------------------------------------------------------
// Launch
// Inputs (metadata order): h, att_feats, p_att_feats, w_h2att, b_h2att,
//                          w_alpha, b_alpha (unused: softmax shift-invariant)
// ---------------------------------------------------------------------------
extern "C" void kernel_launch(void* const* d_in, const int* in_sizes, int n_in,
                              void* d_out, int out_size) {
  (void)in_sizes; (void)n_in; (void)out_size;
  const float* h         = (const float*)d_in[0];
  const float* att_feats = (const float*)d_in[1];
  const float* p_att     = (const float*)d_in[2];
  const float* w_h2att   = (const float*)d_in[3];
  const float* b_h2att   = (const float*)d_in[4];
  const float* w_alpha   = (const float*)d_in[5];
  float* out = (float*)d_out;

  dim3 g1(ATTH / 64, BB / 64, KSPLIT);   // 8 x 4 x 8 = 256 blocks
  gemm_atth_kernel<<<g1, 256>>>(h, w_h2att);
  attn_fused_kernel<<<BB, 512>>>(att_feats, p_att, b_h2att, w_alpha, out);
}